// round 1
// baseline (speedup 1.0000x reference)
#include <cuda_runtime.h>
#include <math.h>

#define LATENT 2048
#define OBS    1024
#define CTRL   512
#define SEQ    4096
#define NCTA   128
#define RPC    16        // latent rows per CTA  (NCTA*RPC == LATENT)
#define NTHR   256

// ---------------- persistent device scratch (no allocations allowed) ----------------
__device__ __align__(16) float g_M  [(size_t)LATENT*LATENT]; // Wout^T Wout
__device__ __align__(16) float g_Gt [(size_t)SEQ*LATENT];    // (Wout^T x_t) laid out [t][l]
__device__ __align__(16) float g_Ut [(size_t)SEQ*LATENT];    // (Win tanh(u_t))  [t][l]
__device__ __align__(16) float g_zpt[(size_t)SEQ*LATENT];    // z_projs (drive)  [t][l]
__device__ __align__(16) float g_fz [2][LATENT];             // double-buffered tanh(z)
__device__ unsigned long long g_bar;

// ---------------- reset kernel: runs before the persistent kernel each replay ----------------
__global__ void reset_kernel() {
  int i = threadIdx.x;
  if (i == 0) g_bar = 0ULL;
  for (int j = i; j < LATENT; j += blockDim.x) { g_fz[0][j] = 0.f; g_fz[1][j] = 0.f; }
}

// ---------------- generic tiled fp32 GEMM ----------------
// C[Md x Nd] row-major, C[m][n] = sum_k a(k,m)*b(k,n)
//   a(k,m) = TA ? A[m*Kd + k] : A[k*Md + m]    (optionally tanh)
//   b(k,n) = TB ? B[n*Kd + k] : B[k*Nd + n]    (optionally tanh)
template<bool TA, bool TB, bool TANHA, bool TANHB>
__global__ void gemm_kernel(const float* __restrict__ A, const float* __restrict__ B,
                            float* __restrict__ C, int Md, int Nd, int Kd)
{
  __shared__ float As[16][68];
  __shared__ float Bs[16][68];
  const int tx = threadIdx.x & 15;
  const int ty = threadIdx.x >> 4;
  const int m0 = blockIdx.y * 64;
  const int n0 = blockIdx.x * 64;
  float acc[4][4];
  #pragma unroll
  for (int i = 0; i < 4; i++)
    #pragma unroll
    for (int j = 0; j < 4; j++) acc[i][j] = 0.f;

  for (int k0 = 0; k0 < Kd; k0 += 16) {
    #pragma unroll
    for (int l = 0; l < 4; l++) {
      int i = threadIdx.x + l * 256;
      int kk, mm;
      if (TA) { kk = i & 15; mm = i >> 4; } else { kk = i >> 6; mm = i & 63; }
      float v = TA ? A[(size_t)(m0 + mm) * Kd + (k0 + kk)]
                   : A[(size_t)(k0 + kk) * Md + (m0 + mm)];
      if (TANHA) v = tanhf(v);
      As[kk][mm] = v;
      int kk2, nn;
      if (TB) { kk2 = i & 15; nn = i >> 4; } else { kk2 = i >> 6; nn = i & 63; }
      float w = TB ? B[(size_t)(n0 + nn) * Kd + (k0 + kk2)]
                   : B[(size_t)(k0 + kk2) * Nd + (n0 + nn)];
      if (TANHB) w = tanhf(w);
      Bs[kk2][nn] = w;
    }
    __syncthreads();
    #pragma unroll
    for (int kk = 0; kk < 16; kk++) {
      float a[4], bb[4];
      #pragma unroll
      for (int i = 0; i < 4; i++) a[i]  = As[kk][ty * 4 + i];
      #pragma unroll
      for (int j = 0; j < 4; j++) bb[j] = Bs[kk][tx * 4 + j];
      #pragma unroll
      for (int i = 0; i < 4; i++)
        #pragma unroll
        for (int j = 0; j < 4; j++)
          acc[i][j] += a[i] * bb[j];
    }
    __syncthreads();
  }
  #pragma unroll
  for (int i = 0; i < 4; i++)
    #pragma unroll
    for (int j = 0; j < 4; j++)
      C[(size_t)(m0 + ty * 4 + i) * Nd + (n0 + tx * 4 + j)] = acc[i][j];
}

// ---------------- persistent sequential kernel ----------------
__device__ __forceinline__ float warp_sum(float v) {
  #pragma unroll
  for (int s = 16; s; s >>= 1) v += __shfl_xor_sync(0xffffffffu, v, s);
  return v;
}

#define SEQ_SMEM ((RPC*LATENT + LATENT + 3*RPC) * 4)  // 139456 bytes

__global__ void __launch_bounds__(NTHR, 1)
seq_kernel(const float* __restrict__ Wr,
           const int* __restrict__ p_it, const float* __restrict__ p_lr,
           float* __restrict__ zs_out)
{
  extern __shared__ float sm[];
  float* Ms  = sm;                    // RPC*LATENT : this CTA's slice of M
  float* fzs = Ms + RPC * LATENT;     // LATENT     : full tanh(z) vector
  float* zl  = fzs + LATENT;          // RPC        : local z rows
  float* dr  = zl + RPC;              // RPC        : local drive rows
  float* gl  = dr + RPC;              // RPC        : local g rows

  const int b    = blockIdx.x;
  const int tid  = threadIdx.x;
  const int w    = tid >> 5, lane = tid & 31;
  const int r0   = 2 * w, r1 = r0 + 1;   // 8 warps x 2 rows = 16 rows
  const int rowb = b * RPC;

  // stage M slice into SMEM once (persists whole kernel)
  {
    const float4* src = (const float4*)(g_M + (size_t)rowb * LATENT);
    float4* dst = (float4*)Ms;
    #pragma unroll 4
    for (int i = tid; i < RPC * LATENT / 4; i += NTHR) dst[i] = src[i];
  }
  if (tid < RPC) zl[tid] = 0.f;

  int n_it = p_it[0];
  if (n_it <= 0 || n_it > 1000000) n_it = (int)(((const long long*)p_it)[0]);
  float lr = p_lr[0];
  if (!(lr > 1e-8f && lr < 16.f)) lr = (float)(((const double*)p_lr)[0]);

  unsigned long long bcnt = 0;
  __syncthreads();

  for (int t = 0; t < SEQ; t++) {
    int par = (int)(((long long)t * n_it) & 1);   // fz buffer parity at step start
    // load fz(z_{t-1}) : used by both the drive matvec and inference iter 0
    {
      const float4* s = (const float4*)(g_fz[par]);
      float4* d4 = (float4*)fzs;
      #pragma unroll
      for (int i = tid; i < LATENT / 4; i += NTHR) d4[i] = __ldcg(s + i);
    }
    if (tid < RPC) gl[tid] = g_Gt[(size_t)t * LATENT + rowb + tid];
    __syncthreads();

    // drive = Wr @ fz + Win tanh(u)   (Wr streamed from L2)
    {
      const float4* a0p = (const float4*)(Wr + (size_t)(rowb + r0) * LATENT);
      const float4* a1p = (const float4*)(Wr + (size_t)(rowb + r1) * LATENT);
      const float4* f4  = (const float4*)fzs;
      float s0 = 0.f, s1 = 0.f;
      #pragma unroll 4
      for (int j = lane; j < LATENT / 4; j += 32) {
        float4 f  = f4[j];
        float4 x0 = __ldg(a0p + j);
        float4 x1 = __ldg(a1p + j);
        s0 += x0.x * f.x + x0.y * f.y + x0.z * f.z + x0.w * f.w;
        s1 += x1.x * f.x + x1.y * f.y + x1.z * f.z + x1.w * f.w;
      }
      s0 = warp_sum(s0); s1 = warp_sum(s1);
      if (lane == 0) {
        dr[r0] = s0 + g_Ut[(size_t)t * LATENT + rowb + r0];
        dr[r1] = s1 + g_Ut[(size_t)t * LATENT + rowb + r1];
      }
    }
    __syncthreads();

    // 20 inference iterations: z -= lr * ((z - drive) - (1-fz^2)*(g - M fz))
    for (int k = 0; k < n_it; k++) {
      const float4* m0p = (const float4*)(Ms + r0 * LATENT);
      const float4* m1p = (const float4*)(Ms + r1 * LATENT);
      const float4* f4  = (const float4*)fzs;
      float s0 = 0.f, s1 = 0.f;
      #pragma unroll 4
      for (int j = lane; j < LATENT / 4; j += 32) {
        float4 f  = f4[j];
        float4 x0 = m0p[j];
        float4 x1 = m1p[j];
        s0 += x0.x * f.x + x0.y * f.y + x0.z * f.z + x0.w * f.w;
        s1 += x1.x * f.x + x1.y * f.y + x1.z * f.z + x1.w * f.w;
      }
      s0 = warp_sum(s0); s1 = warp_sum(s1);
      const int wp = par ^ 1;
      if (lane == 0) {
        float z0 = zl[r0], f0 = fzs[rowb + r0];
        float d0 = (z0 - dr[r0]) - (1.f - f0 * f0) * (gl[r0] - s0);
        z0 -= lr * d0; zl[r0] = z0;
        g_fz[wp][rowb + r0] = tanhf(z0);
        float z1 = zl[r1], f1 = fzs[rowb + r1];
        float d1 = (z1 - dr[r1]) - (1.f - f1 * f1) * (gl[r1] - s1);
        z1 -= lr * d1; zl[r1] = z1;
        g_fz[wp][rowb + r1] = tanhf(z1);
      }
      __syncthreads();
      // ---- grid-wide epoch barrier (one per iteration; fz is double-buffered) ----
      bcnt++;
      if (tid == 0) {
        __threadfence();                          // release published fz
        atomicAdd(&g_bar, 1ULL);
        const unsigned long long tgt = bcnt * (unsigned long long)NCTA;
        while (*((volatile unsigned long long*)&g_bar) < tgt) { __nanosleep(40); }
        __threadfence();                          // acquire
      }
      __syncthreads();
      par = wp;
      if (k + 1 < n_it) {                         // reload updated fz (L2, bypass L1)
        const float4* s = (const float4*)(g_fz[par]);
        float4* d4 = (float4*)fzs;
        #pragma unroll
        for (int i = tid; i < LATENT / 4; i += NTHR) d4[i] = __ldcg(s + i);
        __syncthreads();
      }
    }

    // outputs: zs[:,t] (row-major LATENT x SEQ) and z_projs (drive) as [t][l]
    if (tid < RPC) {
      zs_out[(size_t)(rowb + tid) * SEQ + t] = zl[tid];
      g_zpt[(size_t)t * LATENT + rowb + tid] = dr[tid];
    }
  }
}

// ---------------- launch ----------------
extern "C" void kernel_launch(void* const* d_in, const int* in_sizes, int n_in,
                              void* d_out, int out_size)
{
  const float* inputs   = (const float*)d_in[0];  // (OBS,  SEQ)
  const float* controls = (const float*)d_in[1];  // (CTRL, SEQ)
  const float* Wr       = (const float*)d_in[2];  // (LATENT, LATENT)
  const float* Win      = (const float*)d_in[3];  // (LATENT, CTRL)
  const float* Wout     = (const float*)d_in[4];  // (OBS, LATENT)
  const int*   p_it     = (const int*)d_in[5];
  const float* p_lr     = (const float*)d_in[6];

  float* zs   = (float*)d_out;                       // (LATENT, SEQ)
  float* pred = zs + (size_t)LATENT * SEQ;           // (OBS, SEQ)

  float *pM, *pGt, *pUt, *pZpt;
  cudaGetSymbolAddress((void**)&pM,   g_M);
  cudaGetSymbolAddress((void**)&pGt,  g_Gt);
  cudaGetSymbolAddress((void**)&pUt,  g_Ut);
  cudaGetSymbolAddress((void**)&pZpt, g_zpt);

  cudaFuncSetAttribute(seq_kernel, cudaFuncAttributeMaxDynamicSharedMemorySize, SEQ_SMEM);

  dim3 thr(256);
  // M = Wout^T Wout : C[2048x2048], a(k,m)=Wout[k,m], b(k,n)=Wout[k,n]
  gemm_kernel<false,false,false,false><<<dim3(LATENT/64, LATENT/64), thr>>>(Wout, Wout, pM, LATENT, LATENT, OBS);
  // Gt[t][l] = sum_i inputs[i][t] * Wout[i][l]
  gemm_kernel<false,false,false,false><<<dim3(LATENT/64, SEQ/64), thr>>>(inputs, Wout, pGt, SEQ, LATENT, OBS);
  // Ut[t][l] = sum_c tanh(controls[c][t]) * Win[l][c]
  gemm_kernel<false,true,true,false><<<dim3(LATENT/64, SEQ/64), thr>>>(controls, Win, pUt, SEQ, LATENT, CTRL);

  reset_kernel<<<1, 256>>>();
  seq_kernel<<<NCTA, NTHR, SEQ_SMEM>>>(Wr, p_it, p_lr, zs);

  // pred[i][t] = sum_l Wout[i][l] * tanh(zpt[t][l])
  gemm_kernel<true,true,false,true><<<dim3(SEQ/64, OBS/64), thr>>>(Wout, pZpt, pred, OBS, SEQ, LATENT);
}